// round 4
// baseline (speedup 1.0000x reference)
#include <cuda_runtime.h>
#include <cstdint>

#define MM 512
#define NN 1024
#define WR 16
#define BB 4096
#define G  8            // batch elements per block (16 lanes each -> 128 threads)
#define STRIDE 1032     // padded floats per batch row in smem (1032 % 32 == 8)

// Compressed c2v state: per (cn, batch) -> {m1 bits, m2 bits, signs|am|par, pad}
// 512 * 4096 * 16B = 32 MB device scratch (static __device__, allowed).
__device__ uint4 g_c2v[MM * BB];

__global__ __launch_bounds__(G * 16)
void ldpc_layered_ms_kernel(const float* __restrict__ llr,
                            const int*   __restrict__ H,
                            const int*   __restrict__ iters_p,
                            const int*   __restrict__ cn_order,
                            float*       __restrict__ out)
{
    __shared__ float sh_vn[G * STRIDE];

    const int tid   = threadIdx.x;
    const int lane  = tid & 31;
    const int i     = tid & 15;                 // edge index within row
    const int g     = tid >> 4;                 // local batch index
    const int batch = blockIdx.x * G + g;
    const int gbase = lane & 16;                // 0 for low half, 16 for high half
    const unsigned mask = 0xFFFFu << gbase;     // this group's 16 lanes

    float* vn = sh_vn + g * STRIDE;

    // Load channel LLRs for this batch element (each 16-lane group loads its own row).
    #pragma unroll 4
    for (int n = i; n < NN; n += 16)
        vn[n] = llr[batch * NN + n];
    __syncwarp();

    const int iters = *iters_p;                 // uniform device read (graph-safe)
    const int total = iters * MM;

    int tm = 0;
    for (int t = 0; t < total; ++t) {
        const int cn = __ldg(&cn_order[tm]);
        if (++tm == MM) tm = 0;

        const int idx = __ldg(&H[cn * WR + i]);
        const float v = vn[idx];

        // Reconstruct old c2v from compressed state (0 on first pass over each cn).
        float c2v_old = 0.0f;
        if (t >= MM) {
            const uint4 cc = g_c2v[cn * BB + batch];
            const float m1o = __uint_as_float(cc.x);
            const float m2o = __uint_as_float(cc.y);
            const unsigned pk = cc.z;
            const int am_o = (int)((pk >> 16) & 15u);
            const float amp_o = (i == am_o) ? m2o : m1o;
            const unsigned s = ((pk >> i) ^ (pk >> 20)) & 1u;   // sign_i XOR parity
            c2v_old = s ? -amp_o : amp_o;
        }

        const float v2c = v - c2v_old;
        const unsigned vb  = __float_as_uint(v2c);
        const unsigned neg = vb >> 31;
        const unsigned ab  = vb & 0x7FFFFFFFu;   // |v2c| as order-preserving uint

        // min1 / argmin / min2 / sign parity across the 16-lane group.
        const unsigned min1 = __reduce_min_sync(mask, ab);
        const unsigned eq   = __ballot_sync(mask, ab == min1);
        const int am        = __ffs(eq >> gbase) - 1;
        const unsigned min2 = __reduce_min_sync(mask, (i == am) ? 0x7FFFFFFFu : ab);
        const unsigned sb   = __ballot_sync(mask, neg != 0u);
        const unsigned signs = (sb >> gbase) & 0xFFFFu;
        const unsigned par   = (unsigned)__popc(signs) & 1u;

        // clip(|.|, 20) applied to the two mins == clip of every extrinsic value.
        const float m1 = fminf(__uint_as_float(min1), 20.0f);
        const float m2 = fminf(__uint_as_float(min2), 20.0f);
        const float amp = (i == am) ? m2 : m1;
        const unsigned sl = par ^ neg;
        const float c2v_new = sl ? -amp : amp;

        vn[idx] = v2c + c2v_new;

        if (i == 0) {
            uint4 cc;
            cc.x = __float_as_uint(m1);
            cc.y = __float_as_uint(m2);
            cc.z = signs | ((unsigned)am << 16) | (par << 20);
            cc.w = 0u;
            g_c2v[cn * BB + batch] = cc;
        }
        __syncwarp();   // make this step's vn scatter visible to all group lanes
    }

    // Hard decision output.
    #pragma unroll 4
    for (int n = i; n < NN; n += 16)
        out[batch * NN + n] = (vn[n] < 0.0f) ? 1.0f : 0.0f;
}

extern "C" void kernel_launch(void* const* d_in, const int* in_sizes, int n_in,
                              void* d_out, int out_size)
{
    const float* llr      = (const float*)d_in[0];   // channel_llr [4096,1024] f32
    const int*   H        = (const int*)  d_in[1];   // H_compact   [512,16]    i32
    const int*   iters_p  = (const int*)  d_in[2];   // iters scalar
    const int*   cn_order = (const int*)  d_in[3];   // cn_order    [512]       i32
    float*       out      = (float*)d_out;

    (void)in_sizes; (void)n_in; (void)out_size;

    const int blocks = BB / G;      // 512
    ldpc_layered_ms_kernel<<<blocks, G * 16>>>(llr, H, iters_p, cn_order, out);
}

// round 5
// speedup vs baseline: 1.0718x; 1.0718x over previous
#include <cuda_runtime.h>
#include <cstdint>

#define MM 512
#define NN 1024
#define WR 16
#define BB 4096
#define G  8            // batch elements per block (16 lanes each -> 128 threads)
#define STRIDE 1032     // padded floats per batch row in smem

// Compressed c2v state per (cn, batch): {m1 bits, m2 bits, flip|am, pad} = 16 B.
// flip_i = sign_i XOR parity (parity folded in at store time).
__device__ uint4 g_c2v[MM * BB];

__global__ void init_c2v_kernel()
{
    int idx = blockIdx.x * blockDim.x + threadIdx.x;
    if (idx < MM * BB) g_c2v[idx] = make_uint4(0u, 0u, 0u, 0u);
}

// One layered-MS check-node update for one 16-lane group.
#define STEP(CN, IDX, CC) do {                                              \
    const float v = vn[IDX];                                                \
    /* reconstruct old c2v from compressed state */                         \
    const unsigned pk_o = (CC).z;                                           \
    const int      am_o = (int)((pk_o >> 16) & 15u);                        \
    const unsigned ampo = (i == am_o) ? (CC).y : (CC).x;                    \
    const unsigned sg_o = (pk_o << shl) & 0x80000000u;                      \
    const float c2v_old = __uint_as_float(ampo | sg_o);                     \
    const float v2c = v - c2v_old;                                          \
    const unsigned vb = __float_as_uint(v2c);                               \
    const unsigned ab = vb & 0x7FFFFFFFu;   /* order-preserving |v2c| */    \
    /* depth-2 collectives: min1 -> {eq ballot || min2c redux}; signs dep-1 */ \
    const unsigned sb   = __ballot_sync(mask, vb >= 0x80000000u);           \
    const unsigned min1 = __reduce_min_sync(mask, ab);                      \
    const bool     pe   = (ab == min1);                                     \
    const unsigned eq    = __ballot_sync(mask, pe);                         \
    const unsigned min2c = __reduce_min_sync(mask, pe ? 0x7FFFFFFFu : ab);  \
    const unsigned eqg   = (eq >> gbase) & 0xFFFFu;                         \
    const unsigned signs = (sb >> gbase) & 0xFFFFu;                         \
    const int      am    = __ffs(eqg) - 1;                                  \
    const unsigned m1b   = umin(min1, 0x41A00000u);          /* clip 20 */  \
    const unsigned m2b   = (eqg & (eqg - 1u)) ? m1b                         \
                                              : umin(min2c, 0x41A00000u);   \
    const unsigned ampb  = (i == am) ? m2b : m1b;                           \
    const unsigned par31 = (unsigned)__popc(signs) << 31;                   \
    const unsigned sgn   = (par31 ^ vb) & 0x80000000u;                      \
    const float c2v_new  = __uint_as_float(ampb | sgn);                     \
    vn[IDX] = v2c + c2v_new;                                                \
    if (i == 0) {                                                           \
        const unsigned pm = (unsigned)(-(int)(__popc(signs) & 1));          \
        uint4 nc;                                                           \
        nc.x = m1b;                                                         \
        nc.y = m2b;                                                         \
        nc.z = ((signs ^ pm) & 0xFFFFu) | ((unsigned)am << 16);             \
        nc.w = 0u;                                                          \
        g_c2v[(CN) * BB + batch] = nc;                                      \
    }                                                                       \
    __syncwarp();                                                           \
} while (0)

__global__ __launch_bounds__(G * 16)
void ldpc_layered_ms_kernel(const float* __restrict__ llr,
                            const int*   __restrict__ H,
                            const int*   __restrict__ iters_p,
                            const int*   __restrict__ cn_order,
                            float*       __restrict__ out)
{
    __shared__ float sh_vn[G * STRIDE];

    const int tid   = threadIdx.x;
    const int lane  = tid & 31;
    const int i     = tid & 15;                 // edge index within row
    const int g     = tid >> 4;                 // local batch index
    const int batch = blockIdx.x * G + g;
    const int gbase = lane & 16;                // 0 low half, 16 high half
    const unsigned mask = 0xFFFFu << gbase;
    const int shl   = 31 - i;                   // sign-bit extraction shift

    float* vn = sh_vn + g * STRIDE;

    #pragma unroll 4
    for (int n = i; n < NN; n += 16)
        vn[n] = llr[batch * NN + n];
    __syncwarp();

    const int iters = *iters_p;
    const int total = iters * MM;               // 2560, even

    // ---- software pipeline: prime 2 steps of (cn, idx, c2v) ----
    int cn0 = __ldg(&cn_order[0]);
    int cn1 = __ldg(&cn_order[1]);
    int idx0 = __ldg(&H[cn0 * WR + i]);
    int idx1 = __ldg(&H[cn1 * WR + i]);
    uint4 cc0 = g_c2v[cn0 * BB + batch];        // zero-initialized by init kernel
    uint4 cc1 = g_c2v[cn1 * BB + batch];
    int tm = 2;

    for (int t = 0; t < total; t += 2) {
        // prefetch for step t+2 (cn_{t+2} != cn_t: safe vs this step's store)
        int cnA = __ldg(&cn_order[tm]); if (++tm == MM) tm = 0;
        int idxA = __ldg(&H[cnA * WR + i]);
        uint4 ccA = g_c2v[cnA * BB + batch];

        STEP(cn0, idx0, cc0);

        // prefetch for step t+3
        int cnB = __ldg(&cn_order[tm]); if (++tm == MM) tm = 0;
        int idxB = __ldg(&H[cnB * WR + i]);
        uint4 ccB = g_c2v[cnB * BB + batch];

        STEP(cn1, idx1, cc1);

        cn0 = cnA; idx0 = idxA; cc0 = ccA;
        cn1 = cnB; idx1 = idxB; cc1 = ccB;
    }

    // Hard decision output.
    #pragma unroll 4
    for (int n = i; n < NN; n += 16)
        out[batch * NN + n] = (vn[n] < 0.0f) ? 1.0f : 0.0f;
}

extern "C" void kernel_launch(void* const* d_in, const int* in_sizes, int n_in,
                              void* d_out, int out_size)
{
    const float* llr      = (const float*)d_in[0];   // channel_llr [4096,1024] f32
    const int*   H        = (const int*)  d_in[1];   // H_compact   [512,16]    i32
    const int*   iters_p  = (const int*)  d_in[2];   // iters scalar
    const int*   cn_order = (const int*)  d_in[3];   // cn_order    [512]       i32
    float*       out      = (float*)d_out;

    (void)in_sizes; (void)n_in; (void)out_size;

    init_c2v_kernel<<<(MM * BB + 255) / 256, 256>>>();
    ldpc_layered_ms_kernel<<<BB / G, G * 16>>>(llr, H, iters_p, cn_order, out);
}

// round 6
// speedup vs baseline: 1.5655x; 1.4606x over previous
#include <cuda_runtime.h>
#include <cstdint>

#define MM 512
#define NN 1024
#define WR 16
#define BB 4096
#define G  8            // batch elements per block (16 lanes each -> 128 threads)
#define STRIDE 1032     // padded floats per batch row in smem

// Per-lane c2v state: g_c2v[(cn*BB + batch)*WR + i], fp32. 128 MB static.
__device__ float g_c2v[MM * BB * WR];

// merge two (min1,min2) pairs -> (r1,r2)
#define MERGE(r1, r2, a1, a2, b1, b2) do {                \
    r1 = fminf(a1, b1);                                   \
    r2 = fminf(fmaxf(a1, b1), fminf(a2, b2));             \
} while (0)

// One layered-MS check-node update. No warp collectives, no divergence.
#define STEP(CN, IDX, CO) do {                                              \
    const float v2c = vn[IDX] - (CO);                                       \
    sc[i] = v2c;                                                            \
    __syncwarp();                                                           \
    const float4 s0 = *(const float4*)(sc + 0);                             \
    const float4 s1 = *(const float4*)(sc + 4);                             \
    const float4 s2 = *(const float4*)(sc + 8);                             \
    const float4 s3 = *(const float4*)(sc + 12);                            \
    /* leaves: 8 (min,max) pairs on |.| (abs folds into FMNMX) */           \
    float a1,a2,b1,b2,c1,c2,d1,d2,e1,e2,f1,f2,g1,g2,h1,h2;                  \
    a1 = fminf(fabsf(s0.x), fabsf(s0.y)); a2 = fmaxf(fabsf(s0.x), fabsf(s0.y)); \
    b1 = fminf(fabsf(s0.z), fabsf(s0.w)); b2 = fmaxf(fabsf(s0.z), fabsf(s0.w)); \
    c1 = fminf(fabsf(s1.x), fabsf(s1.y)); c2 = fmaxf(fabsf(s1.x), fabsf(s1.y)); \
    d1 = fminf(fabsf(s1.z), fabsf(s1.w)); d2 = fmaxf(fabsf(s1.z), fabsf(s1.w)); \
    e1 = fminf(fabsf(s2.x), fabsf(s2.y)); e2 = fmaxf(fabsf(s2.x), fabsf(s2.y)); \
    f1 = fminf(fabsf(s2.z), fabsf(s2.w)); f2 = fmaxf(fabsf(s2.z), fabsf(s2.w)); \
    g1 = fminf(fabsf(s3.x), fabsf(s3.y)); g2 = fmaxf(fabsf(s3.x), fabsf(s3.y)); \
    h1 = fminf(fabsf(s3.z), fabsf(s3.w)); h2 = fmaxf(fabsf(s3.z), fabsf(s3.w)); \
    float ab1,ab2,cd1,cd2,ef1,ef2,gh1,gh2, l1,l2, r1,r2, m1,m2;             \
    MERGE(ab1,ab2, a1,a2, b1,b2);                                           \
    MERGE(cd1,cd2, c1,c2, d1,d2);                                           \
    MERGE(ef1,ef2, e1,e2, f1,f2);                                           \
    MERGE(gh1,gh2, g1,g2, h1,h2);                                           \
    MERGE(l1,l2, ab1,ab2, cd1,cd2);                                         \
    MERGE(r1,r2, ef1,ef2, gh1,gh2);                                         \
    MERGE(m1,m2, l1,l2, r1,r2);                                             \
    /* sign parity: xor of all 16 sign bits */                              \
    const unsigned x0 = __float_as_uint(s0.x) ^ __float_as_uint(s0.y)       \
                      ^ __float_as_uint(s0.z) ^ __float_as_uint(s0.w);      \
    const unsigned x1 = __float_as_uint(s1.x) ^ __float_as_uint(s1.y)       \
                      ^ __float_as_uint(s1.z) ^ __float_as_uint(s1.w);      \
    const unsigned x2 = __float_as_uint(s2.x) ^ __float_as_uint(s2.y)       \
                      ^ __float_as_uint(s2.z) ^ __float_as_uint(s2.w);      \
    const unsigned x3 = __float_as_uint(s3.x) ^ __float_as_uint(s3.y)       \
                      ^ __float_as_uint(s3.z) ^ __float_as_uint(s3.w);      \
    const unsigned par = (x0 ^ x1 ^ x2 ^ x3) & 0x80000000u;                 \
    /* leave-one-out amp + clip + sign */                                   \
    const float m1c = fminf(m1, 20.0f);                                     \
    const float m2c = fminf(m2, 20.0f);                                     \
    const float ampf = (fabsf(v2c) == m1) ? m2c : m1c;                      \
    const unsigned sgn = (par ^ __float_as_uint(v2c)) & 0x80000000u;        \
    const float cnew = __uint_as_float(__float_as_uint(ampf) | sgn);        \
    vn[IDX] = v2c + cnew;                                                   \
    g_c2v[((CN) << 16) + cbase] = cnew;                                     \
    __syncwarp();                                                           \
} while (0)

__global__ __launch_bounds__(G * 16)
void ldpc_layered_ms_kernel(const float* __restrict__ llr,
                            const int*   __restrict__ H,
                            const int*   __restrict__ iters_p,
                            const int*   __restrict__ cn_order,
                            float*       __restrict__ out)
{
    __shared__ float sh_vn[G * STRIDE];
    __shared__ float sh_sc[G * WR];

    const int tid   = threadIdx.x;
    const int i     = tid & 15;                 // edge index within row
    const int g     = tid >> 4;                 // local batch index
    const int batch = blockIdx.x * G + g;
    const int cbase = batch * WR + i;           // c2v addressing base

    float* vn = sh_vn + g * STRIDE;
    float* sc = sh_sc + g * WR;

    #pragma unroll 4
    for (int n = i; n < NN; n += 16)
        vn[n] = llr[batch * NN + n];
    __syncwarp();

    const int iters = *iters_p;
    const int total = iters * MM;               // 2560, even

    // ---- software pipeline: prime 2 steps (first pass -> c2v_old = 0) ----
    int cn0  = __ldg(&cn_order[0]);
    int cn1  = __ldg(&cn_order[1]);
    int idx0 = __ldg(&H[cn0 * WR + i]);
    int idx1 = __ldg(&H[cn1 * WR + i]);
    float co0 = 0.0f, co1 = 0.0f;
    int tm = 2;

    for (int t = 0; t < total; t += 2) {
        // prefetch for step t+2 (distinct cn from t: safe vs this step's store)
        int   cnA  = __ldg(&cn_order[tm]); if (++tm == MM) tm = 0;
        int   idxA = __ldg(&H[cnA * WR + i]);
        float coA  = g_c2v[(cnA << 16) + cbase];
        const bool fpA = (t + 2) < MM;          // first pass over cnA?

        STEP(cn0, idx0, co0);

        // prefetch for step t+3
        int   cnB  = __ldg(&cn_order[tm]); if (++tm == MM) tm = 0;
        int   idxB = __ldg(&H[cnB * WR + i]);
        float coB  = g_c2v[(cnB << 16) + cbase];
        const bool fpB = (t + 3) < MM;

        STEP(cn1, idx1, co1);

        cn0 = cnA; idx0 = idxA; co0 = fpA ? 0.0f : coA;
        cn1 = cnB; idx1 = idxB; co1 = fpB ? 0.0f : coB;
    }

    // Hard decision output.
    #pragma unroll 4
    for (int n = i; n < NN; n += 16)
        out[batch * NN + n] = (vn[n] < 0.0f) ? 1.0f : 0.0f;
}

extern "C" void kernel_launch(void* const* d_in, const int* in_sizes, int n_in,
                              void* d_out, int out_size)
{
    const float* llr      = (const float*)d_in[0];   // channel_llr [4096,1024] f32
    const int*   H        = (const int*)  d_in[1];   // H_compact   [512,16]    i32
    const int*   iters_p  = (const int*)  d_in[2];   // iters scalar
    const int*   cn_order = (const int*)  d_in[3];   // cn_order    [512]       i32
    float*       out      = (float*)d_out;

    (void)in_sizes; (void)n_in; (void)out_size;

    ldpc_layered_ms_kernel<<<BB / G, G * 16>>>(llr, H, iters_p, cn_order, out);
}

// round 7
// speedup vs baseline: 1.8841x; 1.2035x over previous
#include <cuda_runtime.h>
#include <cstdint>

#define MM 512
#define NN 1024
#define WR 16
#define BB 4096
#define BPB 8            // batches per block (1 warp, 4 lanes per batch)
#define VSTRIDE 1028     // padded floats per batch row in smem (16B aligned, bank shift 4/batch)

// Per-lane c2v state: g_c2v[(cn*BB + batch)*4 + li] = float4 (this lane's 4 edges). 128 MB.
__device__ float4 g_c2v[MM * BB * 4];

// Prefetch slot S for global step index T (first pass over a cn -> c2v_old = 0).
#define PREFETCH(S, T) do {                                                  \
    cn##S = __ldg(&cn_order[tm]); if (++tm == MM) tm = 0;                    \
    idx##S = __ldg((const int4*)H + cn##S * 4 + li);                         \
    co##S = g_c2v[(cn##S * BB + batch) * 4 + li];                            \
    if ((T) < MM) co##S = make_float4(0.f, 0.f, 0.f, 0.f);                   \
} while (0)

// One layered-MS check-node update (4 edges in-thread + 2-stage quad butterfly).
#define STEP(S) do {                                                         \
    const int4   idx = idx##S;                                               \
    const float4 co  = co##S;                                                \
    const float t0 = vn[idx.x] - co.x;                                       \
    const float t1 = vn[idx.y] - co.y;                                       \
    const float t2 = vn[idx.z] - co.z;                                       \
    const float t3 = vn[idx.w] - co.w;                                       \
    const float p1 = fminf(fabsf(t0), fabsf(t1));                            \
    const float p2 = fmaxf(fabsf(t0), fabsf(t1));                            \
    const float q1 = fminf(fabsf(t2), fabsf(t3));                            \
    const float q2 = fmaxf(fabsf(t2), fabsf(t3));                            \
    float m1 = fminf(p1, q1);                                                \
    float m2 = fminf(fmaxf(p1, q1), fminf(p2, q2));                          \
    unsigned par = __float_as_uint(t0) ^ __float_as_uint(t1)                 \
                 ^ __float_as_uint(t2) ^ __float_as_uint(t3);                \
    {   const float n1 = __shfl_xor_sync(0xffffffffu, m1, 1);                \
        const float n2 = __shfl_xor_sync(0xffffffffu, m2, 1);                \
        const unsigned np = __shfl_xor_sync(0xffffffffu, par, 1);            \
        m2 = fminf(fmaxf(m1, n1), fminf(m2, n2));                            \
        m1 = fminf(m1, n1); par ^= np; }                                     \
    {   const float n1 = __shfl_xor_sync(0xffffffffu, m1, 2);                \
        const float n2 = __shfl_xor_sync(0xffffffffu, m2, 2);                \
        const unsigned np = __shfl_xor_sync(0xffffffffu, par, 2);            \
        m2 = fminf(fmaxf(m1, n1), fminf(m2, n2));                            \
        m1 = fminf(m1, n1); par ^= np; }                                     \
    par &= 0x80000000u;                                                      \
    const float m1c = fminf(m1, 20.0f);                                      \
    const float m2c = fminf(m2, 20.0f);                                      \
    const float a0 = (fabsf(t0) == m1) ? m2c : m1c;                          \
    const float a1 = (fabsf(t1) == m1) ? m2c : m1c;                          \
    const float a2 = (fabsf(t2) == m1) ? m2c : m1c;                          \
    const float a3 = (fabsf(t3) == m1) ? m2c : m1c;                          \
    const float c0 = __uint_as_float(__float_as_uint(a0) |                   \
                     ((par ^ __float_as_uint(t0)) & 0x80000000u));           \
    const float c1 = __uint_as_float(__float_as_uint(a1) |                   \
                     ((par ^ __float_as_uint(t1)) & 0x80000000u));           \
    const float c2 = __uint_as_float(__float_as_uint(a2) |                   \
                     ((par ^ __float_as_uint(t2)) & 0x80000000u));           \
    const float c3 = __uint_as_float(__float_as_uint(a3) |                   \
                     ((par ^ __float_as_uint(t3)) & 0x80000000u));           \
    vn[idx.x] = t0 + c0;                                                     \
    vn[idx.y] = t1 + c1;                                                     \
    vn[idx.z] = t2 + c2;                                                     \
    vn[idx.w] = t3 + c3;                                                     \
    g_c2v[(cn##S * BB + batch) * 4 + li] = make_float4(c0, c1, c2, c3);      \
    __syncwarp();                                                            \
} while (0)

__global__ __launch_bounds__(32)
void ldpc_layered_ms_kernel(const float* __restrict__ llr,
                            const int*   __restrict__ H,
                            const int*   __restrict__ iters_p,
                            const int*   __restrict__ cn_order,
                            float*       __restrict__ out)
{
    __shared__ float sh_vn[BPB * VSTRIDE];

    const int lane  = threadIdx.x;              // 0..31
    const int li    = lane & 3;                 // quad-lane (edge group)
    const int g     = lane >> 2;                // local batch 0..7
    const int batch = blockIdx.x * BPB + g;

    float* vn = sh_vn + g * VSTRIDE;

    // Load channel LLRs (float4 per lane per iteration).
    const float4* src = (const float4*)(llr + batch * NN);
    #pragma unroll 4
    for (int k = 0; k < NN / 16; ++k) {         // 64 iters
        const int n4 = li + 4 * k;
        *(float4*)(vn + 4 * n4) = src[n4];
    }
    __syncwarp();

    const int iters = *iters_p;
    const int total = iters * MM;               // multiple of 4 (MM = 512)

    // ---- 4-deep software pipeline ----
    int  cnA, cnB, cnC, cnD;
    int4 idxA, idxB, idxC, idxD;
    float4 coA, coB, coC, coD;
    int tm = 0;
    PREFETCH(A, 0);
    PREFETCH(B, 1);
    PREFETCH(C, 2);
    PREFETCH(D, 3);

    for (int t = 0; t < total; t += 4) {
        STEP(A); PREFETCH(A, t + 4);
        STEP(B); PREFETCH(B, t + 5);
        STEP(C); PREFETCH(C, t + 6);
        STEP(D); PREFETCH(D, t + 7);
    }

    // Hard decision output (float4 per lane per iteration).
    float4* dst = (float4*)(out + batch * NN);
    #pragma unroll 4
    for (int k = 0; k < NN / 16; ++k) {
        const int n4 = li + 4 * k;
        const float* p = vn + 4 * n4;
        dst[n4] = make_float4(p[0] < 0.0f ? 1.0f : 0.0f,
                              p[1] < 0.0f ? 1.0f : 0.0f,
                              p[2] < 0.0f ? 1.0f : 0.0f,
                              p[3] < 0.0f ? 1.0f : 0.0f);
    }
}

extern "C" void kernel_launch(void* const* d_in, const int* in_sizes, int n_in,
                              void* d_out, int out_size)
{
    const float* llr      = (const float*)d_in[0];   // channel_llr [4096,1024] f32
    const int*   H        = (const int*)  d_in[1];   // H_compact   [512,16]    i32
    const int*   iters_p  = (const int*)  d_in[2];   // iters scalar
    const int*   cn_order = (const int*)  d_in[3];   // cn_order    [512]       i32
    float*       out      = (float*)d_out;

    (void)in_sizes; (void)n_in; (void)out_size;

    ldpc_layered_ms_kernel<<<BB / BPB, 32>>>(llr, H, iters_p, cn_order, out);
}